// round 1
// baseline (speedup 1.0000x reference)
#include <cuda_runtime.h>
#include <math.h>

#define T_TOK 2048
#define NL    12
#define DM    768
#define FL    2048

#define BM 128
#define BN 128
#define BK 16

// Fallback scratch if the harness output is x_hat-only (acts must live somewhere).
__device__ float g_acts_scratch[(size_t)T_TOK * NL * FL];

// ---------------------------------------------------------------------------
// Packed f32x2 helpers (Blackwell-only; ptxas never auto-fuses into FFMA2)
// ---------------------------------------------------------------------------
__device__ __forceinline__ unsigned long long bcast2(float a) {
    unsigned long long r;
    asm("mov.b64 %0, {%1,%1};" : "=l"(r) : "f"(a));
    return r;
}
__device__ __forceinline__ void ffma2(unsigned long long& c, unsigned long long a,
                                      unsigned long long b) {
    asm("fma.rn.f32x2 %0, %1, %2, %0;" : "+l"(c) : "l"(a), "l"(b));
}
__device__ __forceinline__ float2 unpack2(unsigned long long v) {
    float2 r;
    asm("mov.b64 {%0,%1}, %2;" : "=f"(r.x), "=f"(r.y) : "l"(v));
    return r;
}

// ---------------------------------------------------------------------------
// Encode: for each layer l, H_l[T,F] = X_l[T,D] @ We_l[D,F]; fp32-exact so the
// JumpReLU threshold decisions match the reference. Writes h and acts.
// ---------------------------------------------------------------------------
__global__ __launch_bounds__(256, 2)
void encode_kernel(const float* __restrict__ X,
                   const float* __restrict__ WE,
                   const float* __restrict__ TH,
                   float* __restrict__ H,          // may be null
                   float* __restrict__ A) {
    const int l  = blockIdx.z;
    const int bm = blockIdx.y * BM;   // token tile
    const int bn = blockIdx.x * BN;   // feature tile

    const float* Ag = X + (size_t)l * DM;             // A[t,d], row stride NL*DM
    const float* Bg = WE + (size_t)l * DM * FL;       // B[d,f], row stride FL

    __shared__ float As[2][BK][BM + 4];
    __shared__ float Bs[2][BK][BN];

    const int tid  = threadIdx.x;
    const int arow = tid >> 2;            // 0..63  (rows arow, arow+64)
    const int akq  = (tid & 3) << 2;      // 0,4,8,12
    const int brow = tid >> 5;            // 0..7   (rows brow, brow+8)
    const int bcol = (tid & 31) << 2;

    const int tm = (tid >> 4) << 3;
    const int tn = (tid & 15) << 3;

    unsigned long long acc[8][4];
#pragma unroll
    for (int i = 0; i < 8; i++)
#pragma unroll
        for (int jj = 0; jj < 4; jj++) acc[i][jj] = 0ULL;

    const int NKT = DM / BK;  // 48

    float4 pa0, pa1, pb0, pb1;
    // preload tile 0
    pa0 = *(const float4*)(Ag + (size_t)(bm + arow)      * (NL * DM) + akq);
    pa1 = *(const float4*)(Ag + (size_t)(bm + arow + 64) * (NL * DM) + akq);
    pb0 = *(const float4*)(Bg + (size_t)(brow)     * FL + bn + bcol);
    pb1 = *(const float4*)(Bg + (size_t)(brow + 8) * FL + bn + bcol);
    As[0][akq + 0][arow] = pa0.x; As[0][akq + 1][arow] = pa0.y;
    As[0][akq + 2][arow] = pa0.z; As[0][akq + 3][arow] = pa0.w;
    As[0][akq + 0][arow + 64] = pa1.x; As[0][akq + 1][arow + 64] = pa1.y;
    As[0][akq + 2][arow + 64] = pa1.z; As[0][akq + 3][arow + 64] = pa1.w;
    *(float4*)&Bs[0][brow][bcol]     = pb0;
    *(float4*)&Bs[0][brow + 8][bcol] = pb1;
    __syncthreads();

    int buf = 0;
    for (int kt = 0; kt < NKT; kt++) {
        if (kt + 1 < NKT) {
            const int k0 = (kt + 1) * BK;
            pa0 = *(const float4*)(Ag + (size_t)(bm + arow)      * (NL * DM) + k0 + akq);
            pa1 = *(const float4*)(Ag + (size_t)(bm + arow + 64) * (NL * DM) + k0 + akq);
            pb0 = *(const float4*)(Bg + (size_t)(k0 + brow)     * FL + bn + bcol);
            pb1 = *(const float4*)(Bg + (size_t)(k0 + brow + 8) * FL + bn + bcol);
        }
#pragma unroll
        for (int k = 0; k < BK; k++) {
            unsigned long long bv[4];
#pragma unroll
            for (int jj = 0; jj < 4; jj++)
                bv[jj] = *(const unsigned long long*)&Bs[buf][k][tn + jj * 2];
#pragma unroll
            for (int i = 0; i < 8; i++) {
                unsigned long long av = bcast2(As[buf][k][tm + i]);
#pragma unroll
                for (int jj = 0; jj < 4; jj++) ffma2(acc[i][jj], av, bv[jj]);
            }
        }
        if (kt + 1 < NKT) {
            const int nb = buf ^ 1;
            As[nb][akq + 0][arow] = pa0.x; As[nb][akq + 1][arow] = pa0.y;
            As[nb][akq + 2][arow] = pa0.z; As[nb][akq + 3][arow] = pa0.w;
            As[nb][akq + 0][arow + 64] = pa1.x; As[nb][akq + 1][arow + 64] = pa1.y;
            As[nb][akq + 2][arow + 64] = pa1.z; As[nb][akq + 3][arow + 64] = pa1.w;
            *(float4*)&Bs[nb][brow][bcol]     = pb0;
            *(float4*)&Bs[nb][brow + 8][bcol] = pb1;
        }
        __syncthreads();
        buf ^= 1;
    }

    // Epilogue: JumpReLU with exact thresholds
    float thr[8];
#pragma unroll
    for (int jj = 0; jj < 8; jj++)
        thr[jj] = expf(TH[l * FL + bn + tn + jj]);

#pragma unroll
    for (int i = 0; i < 8; i++) {
        const int trow = bm + tm + i;
        const size_t base = (size_t)trow * (NL * FL) + (size_t)l * FL + bn + tn;
        float v[8];
#pragma unroll
        for (int jj = 0; jj < 4; jj++) {
            float2 c = unpack2(acc[i][jj]);
            v[jj * 2] = c.x; v[jj * 2 + 1] = c.y;
        }
        if (H) {
            *(float4*)(H + base)     = make_float4(v[0], v[1], v[2], v[3]);
            *(float4*)(H + base + 4) = make_float4(v[4], v[5], v[6], v[7]);
        }
        float a[8];
#pragma unroll
        for (int jj = 0; jj < 8; jj++) a[jj] = (v[jj] > thr[jj]) ? v[jj] : 0.0f;
        *(float4*)(A + base)     = make_float4(a[0], a[1], a[2], a[3]);
        *(float4*)(A + base + 4) = make_float4(a[4], a[5], a[6], a[7]);
    }
}

// ---------------------------------------------------------------------------
// Decode: x_hat[:, j, :] = sum_{i<=j} acts[:, i, :] @ w_d[i, j]
// K flattened over (i, f); acts columns are contiguous in k = i*FL + f.
// j mapped descending over blockIdx.z so the largest K-loops launch first.
// ---------------------------------------------------------------------------
__global__ __launch_bounds__(256, 2)
void decode_kernel(const float* __restrict__ ACT,
                   const float* __restrict__ WD,
                   float* __restrict__ XH) {
    const int j  = (NL - 1) - blockIdx.z;
    const int bm = blockIdx.y * BM;   // token tile
    const int bn = blockIdx.x * BN;   // d tile (6 tiles of 128)

    const size_t bstride_i = (size_t)NL * FL * DM;        // w_d i-stride
    const float* Bg = WD + (size_t)j * FL * DM;           // + i*bstride_i + f*DM

    __shared__ float As[2][BK][BM + 4];
    __shared__ float Bs[2][BK][BN];

    const int tid  = threadIdx.x;
    const int arow = tid >> 2;
    const int akq  = (tid & 3) << 2;
    const int brow = tid >> 5;
    const int bcol = (tid & 31) << 2;

    const int tm = (tid >> 4) << 3;
    const int tn = (tid & 15) << 3;

    unsigned long long acc[8][4];
#pragma unroll
    for (int i = 0; i < 8; i++)
#pragma unroll
        for (int jj = 0; jj < 4; jj++) acc[i][jj] = 0ULL;

    const int NKT = (j + 1) * (FL / BK);   // (j+1)*128 k-tiles

    float4 pa0, pa1, pb0, pb1;
    // preload k-tile 0 (i=0, f0=0)
    pa0 = *(const float4*)(ACT + (size_t)(bm + arow)      * (NL * FL) + akq);
    pa1 = *(const float4*)(ACT + (size_t)(bm + arow + 64) * (NL * FL) + akq);
    pb0 = *(const float4*)(Bg + (size_t)(brow)     * DM + bn + bcol);
    pb1 = *(const float4*)(Bg + (size_t)(brow + 8) * DM + bn + bcol);
    As[0][akq + 0][arow] = pa0.x; As[0][akq + 1][arow] = pa0.y;
    As[0][akq + 2][arow] = pa0.z; As[0][akq + 3][arow] = pa0.w;
    As[0][akq + 0][arow + 64] = pa1.x; As[0][akq + 1][arow + 64] = pa1.y;
    As[0][akq + 2][arow + 64] = pa1.z; As[0][akq + 3][arow + 64] = pa1.w;
    *(float4*)&Bs[0][brow][bcol]     = pb0;
    *(float4*)&Bs[0][brow + 8][bcol] = pb1;
    __syncthreads();

    int buf = 0;
    for (int kt = 0; kt < NKT; kt++) {
        if (kt + 1 < NKT) {
            const int ktn = kt + 1;
            const int k0  = ktn * BK;                 // acts column base
            const int ii  = ktn >> 7;                 // decoder layer i
            const int f0  = (ktn & 127) << 4;         // feature row base
            const float* bb = Bg + (size_t)ii * bstride_i + (size_t)f0 * DM;
            pa0 = *(const float4*)(ACT + (size_t)(bm + arow)      * (NL * FL) + k0 + akq);
            pa1 = *(const float4*)(ACT + (size_t)(bm + arow + 64) * (NL * FL) + k0 + akq);
            pb0 = *(const float4*)(bb + (size_t)(brow)     * DM + bn + bcol);
            pb1 = *(const float4*)(bb + (size_t)(brow + 8) * DM + bn + bcol);
        }
#pragma unroll
        for (int k = 0; k < BK; k++) {
            unsigned long long bv[4];
#pragma unroll
            for (int jj = 0; jj < 4; jj++)
                bv[jj] = *(const unsigned long long*)&Bs[buf][k][tn + jj * 2];
#pragma unroll
            for (int i = 0; i < 8; i++) {
                unsigned long long av = bcast2(As[buf][k][tm + i]);
#pragma unroll
                for (int jj = 0; jj < 4; jj++) ffma2(acc[i][jj], av, bv[jj]);
            }
        }
        if (kt + 1 < NKT) {
            const int nb = buf ^ 1;
            As[nb][akq + 0][arow] = pa0.x; As[nb][akq + 1][arow] = pa0.y;
            As[nb][akq + 2][arow] = pa0.z; As[nb][akq + 3][arow] = pa0.w;
            As[nb][akq + 0][arow + 64] = pa1.x; As[nb][akq + 1][arow + 64] = pa1.y;
            As[nb][akq + 2][arow + 64] = pa1.z; As[nb][akq + 3][arow + 64] = pa1.w;
            *(float4*)&Bs[nb][brow][bcol]     = pb0;
            *(float4*)&Bs[nb][brow + 8][bcol] = pb1;
        }
        __syncthreads();
        buf ^= 1;
    }

#pragma unroll
    for (int i = 0; i < 8; i++) {
        const int trow = bm + tm + i;
        const size_t base = (size_t)trow * (NL * DM) + (size_t)j * DM + bn + tn;
        float v[8];
#pragma unroll
        for (int jj = 0; jj < 4; jj++) {
            float2 c = unpack2(acc[i][jj]);
            v[jj * 2] = c.x; v[jj * 2 + 1] = c.y;
        }
        *(float4*)(XH + base)     = make_float4(v[0], v[1], v[2], v[3]);
        *(float4*)(XH + base + 4) = make_float4(v[4], v[5], v[6], v[7]);
    }
}

// ---------------------------------------------------------------------------
extern "C" void kernel_launch(void* const* d_in, const int* in_sizes, int n_in,
                              void* d_out, int out_size) {
    const float* x  = (const float*)d_in[0];   // [T, L, D]
    const float* we = (const float*)d_in[1];   // [L, D, F]
    const float* wd = (const float*)d_in[2];   // [L, L, F, D]
    const float* th = (const float*)d_in[3];   // [L, F]
    float* out = (float*)d_out;

    const long long HE = (long long)T_TOK * NL * FL;   // 50,331,648
    const long long XE = (long long)T_TOK * NL * DM;   // 18,874,368

    float *hp, *ap, *xp;
    if ((long long)out_size >= 2 * HE + XE) {
        // Standard layout: concat(h, acts, x_hat)
        hp = out;
        ap = out + HE;
        xp = out + 2 * HE;
    } else {
        // Fallback: x_hat only; acts goes to device scratch
        hp = nullptr;
        float* sp = nullptr;
        cudaGetSymbolAddress((void**)&sp, g_acts_scratch);
        ap = sp;
        xp = out;
    }

    dim3 blk(256);
    encode_kernel<<<dim3(FL / BN, T_TOK / BM, NL), blk>>>(x, we, th, hp, ap);
    decode_kernel<<<dim3(DM / BN, T_TOK / BM, NL), blk>>>(ap, wd, xp);
}